// round 11
// baseline (speedup 1.0000x reference)
#include <cuda_runtime.h>
#include <cuda_bf16.h>
#include <cstdint>

#define Bsz 64
#define Tlen 1024
#define Idim 256
#define Hdim 512
#define G4H  2048
#define NBLK 128
#define NGRP 4            // independent batch groups
#define GBLK 32           // unit-blocks per group

// ---------------- device scratch ----------------
__device__ float          g_pre[(size_t)Bsz * Tlen * G4H];   // [T][B][4H]
__device__ __nv_bfloat16  g_whi[G4H * Hdim];                 // w_hh split
__device__ __nv_bfloat16  g_wlo[G4H * Hdim];
__device__ __nv_bfloat16  g_wihi[G4H * Idim];                // w_ih split
__device__ __nv_bfloat16  g_wilo[G4H * Idim];
__device__ __nv_bfloat16  g_xhi[(size_t)Bsz * Tlen * Idim];  // x split
__device__ __nv_bfloat16  g_xlo[(size_t)Bsz * Tlen * Idim];
__device__ __nv_bfloat16  g_hh[2][Bsz * Hdim];
__device__ __nv_bfloat16  g_hl[2][Bsz * Hdim];
__device__ unsigned       g_cnt[NGRP * 32];                  // per-group counters, 128B apart

// ---------------- helpers ----------------
__device__ __forceinline__ uint32_t smem_u32(const void* p) {
    uint32_t a;
    asm("{ .reg .u64 t; cvta.to.shared.u64 t, %1; cvt.u32.u64 %0, t; }" : "=r"(a) : "l"(p));
    return a;
}
__device__ __forceinline__ void ldsm4(uint32_t (&r)[4], uint32_t addr) {
    asm volatile("ldmatrix.sync.aligned.m8n8.x4.shared.b16 {%0,%1,%2,%3}, [%4];"
                 : "=r"(r[0]), "=r"(r[1]), "=r"(r[2]), "=r"(r[3]) : "r"(addr));
}
__device__ __forceinline__ void mma16816(float (&d)[4], const uint32_t (&a)[4],
                                         uint32_t b0, uint32_t b1) {
    asm volatile("mma.sync.aligned.m16n8k16.row.col.f32.bf16.bf16.f32 "
                 "{%0,%1,%2,%3}, {%4,%5,%6,%7}, {%8,%9}, {%0,%1,%2,%3};"
                 : "+f"(d[0]), "+f"(d[1]), "+f"(d[2]), "+f"(d[3])
                 : "r"(a[0]), "r"(a[1]), "r"(a[2]), "r"(a[3]), "r"(b0), "r"(b1));
}
__device__ __forceinline__ void split1(float v, __nv_bfloat16* hi, __nv_bfloat16* lo) {
    __nv_bfloat16 h = __float2bfloat16(v);
    *hi = h;
    *lo = __float2bfloat16(v - __bfloat162float(h));
}
__device__ __forceinline__ void red_release_add(unsigned* p) {
    asm volatile("red.release.gpu.global.add.u32 [%0], 1;" :: "l"(p) : "memory");
}
__device__ __forceinline__ unsigned ld_acquire(const unsigned* p) {
    unsigned v;
    asm volatile("ld.acquire.gpu.global.u32 %0, [%1];" : "=r"(v) : "l"(p) : "memory");
    return v;
}
__device__ __forceinline__ float fast_sigmoid(float x) {
    return __fdividef(1.f, 1.f + __expf(-x));
}
__device__ __forceinline__ float fast_tanh(float x) {
    return 1.f - __fdividef(2.f, __expf(2.f * x) + 1.f);
}
__device__ __forceinline__ void cp_async16(uint32_t smem_addr, const void* gptr) {
    asm volatile("cp.async.cg.shared.global [%0], [%1], 16;"
                 :: "r"(smem_addr), "l"(gptr) : "memory");
}
__device__ __forceinline__ void cp_commit() {
    asm volatile("cp.async.commit_group;" ::: "memory");
}
template <int N>
__device__ __forceinline__ void cp_wait() {
    asm volatile("cp.async.wait_group %0;" :: "n"(N) : "memory");
}

// ---------------- prologue ----------------
__global__ void prep_kernel(const float* __restrict__ x,
                            const float* __restrict__ w_ih,
                            const float* __restrict__ w_hh) {
    int idx = blockIdx.x * blockDim.x + threadIdx.x;
    if (idx < NGRP * 32) g_cnt[idx] = 0u;
    if (idx < 16384) {
        ((uint32_t*)g_hh[0])[idx] = 0u;
        ((uint32_t*)g_hl[0])[idx] = 0u;
    }
    if (idx < G4H * Hdim) split1(w_hh[idx], g_whi + idx, g_wlo + idx);
    if (idx < G4H * Idim) split1(w_ih[idx], g_wihi + idx, g_wilo + idx);
    split1(x[idx], g_xhi + idx, g_xlo + idx);
}

// ---------------- Kernel A: tensor-core pre-GEMM (unchanged, proven) ----------------
#define GS 36
#define TILE_W (128 * GS)
__global__ void __launch_bounds__(256) gemm_pre(const float* __restrict__ bih,
                                                const float* __restrict__ bhh) {
    extern __shared__ uint32_t sm[];
    uint32_t* xs_hi = sm;
    uint32_t* xs_lo = sm + TILE_W;
    uint32_t* ws_hi = sm + 2 * TILE_W;
    uint32_t* ws_lo = sm + 3 * TILE_W;

    const int tid = threadIdx.x;
    const int lane = tid & 31, wid = tid >> 5;
    const int wm = wid & 1, wn = wid >> 1;
    const int m0 = blockIdx.y * 128;
    const int n0 = blockIdx.x * 128;

    const uint32_t a_off = (uint32_t)(((lane & 7) + ((lane >> 3) & 1) * 8) * GS
                                      + ((lane >> 4) & 1) * 4);
    const uint32_t b_off = (uint32_t)((((lane >> 4) & 1) * 8 + (lane & 7)) * GS
                                      + ((lane >> 3) & 1) * 4);
    const uint32_t axh = smem_u32(xs_hi) + (a_off + (wm * 64) * GS) * 4;
    const uint32_t axl = smem_u32(xs_lo) + (a_off + (wm * 64) * GS) * 4;
    const uint32_t bwh = smem_u32(ws_hi) + (b_off + (wn * 32) * GS) * 4;
    const uint32_t bwl = smem_u32(ws_lo) + (b_off + (wn * 32) * GS) * 4;

    float d[4][4][4];
#pragma unroll
    for (int i = 0; i < 4; i++)
#pragma unroll
        for (int j = 0; j < 4; j++)
#pragma unroll
            for (int r = 0; r < 4; r++) d[i][j][r] = 0.f;

    for (int kc = 0; kc < Idim / 64; kc++) {
#pragma unroll
        for (int i = 0; i < 4; i++) {
            int idx = tid + i * 256;
            int row = idx >> 3, q = idx & 7;
            uint32_t dst = row * GS + q * 4;
            *(uint4*)(xs_hi + dst) = *((const uint4*)(g_xhi + (size_t)(m0 + row) * Idim + kc * 64) + q);
            *(uint4*)(xs_lo + dst) = *((const uint4*)(g_xlo + (size_t)(m0 + row) * Idim + kc * 64) + q);
            *(uint4*)(ws_hi + dst) = *((const uint4*)(g_wihi + (size_t)(n0 + row) * Idim + kc * 64) + q);
            *(uint4*)(ws_lo + dst) = *((const uint4*)(g_wilo + (size_t)(n0 + row) * Idim + kc * 64) + q);
        }
        __syncthreads();

#pragma unroll
        for (int kt = 0; kt < 4; kt++) {
            uint32_t ah[4][4], al[4][4];
#pragma unroll
            for (int mi = 0; mi < 4; mi++) {
                uint32_t o = (mi * 16 * GS + kt * 8) * 4;
                ldsm4(ah[mi], axh + o);
                ldsm4(al[mi], axl + o);
            }
            uint2 bh[4], bl[4];
#pragma unroll
            for (int ni = 0; ni < 2; ni++) {
                uint32_t o = (ni * 16 * GS + kt * 8) * 4;
                uint32_t th[4], tl[4];
                ldsm4(th, bwh + o);
                ldsm4(tl, bwl + o);
                bh[ni * 2]     = make_uint2(th[0], th[1]);
                bh[ni * 2 + 1] = make_uint2(th[2], th[3]);
                bl[ni * 2]     = make_uint2(tl[0], tl[1]);
                bl[ni * 2 + 1] = make_uint2(tl[2], tl[3]);
            }
#pragma unroll
            for (int mi = 0; mi < 4; mi++)
#pragma unroll
                for (int n8 = 0; n8 < 4; n8++) {
                    mma16816(d[mi][n8], ah[mi], bh[n8].x, bh[n8].y);
                    mma16816(d[mi][n8], ah[mi], bl[n8].x, bl[n8].y);
                    mma16816(d[mi][n8], al[mi], bh[n8].x, bh[n8].y);
                }
        }
        __syncthreads();
    }

#pragma unroll
    for (int n8 = 0; n8 < 4; n8++) {
        int col = n0 + wn * 32 + n8 * 8 + (lane & 3) * 2;
        float bx = __ldg(bih + col) + __ldg(bhh + col);
        float by = __ldg(bih + col + 1) + __ldg(bhh + col + 1);
#pragma unroll
        for (int mi = 0; mi < 4; mi++) {
            int row0 = m0 + wm * 64 + mi * 16 + (lane >> 2);
            int row1 = row0 + 8;
            size_t dr0 = ((size_t)(row0 & (Tlen - 1)) * Bsz + (row0 >> 10)) * G4H;
            size_t dr1 = ((size_t)(row1 & (Tlen - 1)) * Bsz + (row1 >> 10)) * G4H;
            *(float2*)(g_pre + dr0 + col) = make_float2(d[mi][n8][0] + bx, d[mi][n8][1] + by);
            *(float2*)(g_pre + dr1 + col) = make_float2(d[mi][n8][2] + bx, d[mi][n8][3] + by);
        }
    }
}

// ---------------- Kernel B: batch-sharded persistent scan ----------------
// R10 structure with cp.async.cg two-group staging pipeline: all 16 copies
// issued immediately after the spin, half-1 completes under MMA half-0.
#define OFF_HHI   0                     // 16 rows x 260 words
#define OFF_HLO   4160
#define OFF_BF    8320                  // 8192 uint4 = 32768 words
#define OFF_HSHI  41088                 // 16x16 bf16 = 128 words
#define OFF_HSLO  41216                 // 128 words
#define OFF_HSF   41344                 // 16x16 f32 = 256 words
#define SCAN_WORDS 41600                // 166400 bytes

__global__ void __launch_bounds__(128) lstm_scan(float* __restrict__ out,
                                                 float* __restrict__ hn,
                                                 float* __restrict__ cn) {
    extern __shared__ uint32_t smw[];
    const int tid = threadIdx.x;
    const int lane = tid & 31, w = tid >> 5;
    const int bg = blockIdx.x >> 5, ug = blockIdx.x & 31;
    const int j0 = ug * 16, b0 = bg * 16;
    unsigned* cnt = &g_cnt[bg * 32];

    // ---- fill B fragments once (validated) ----
    uint4* BF4 = (uint4*)(smw + OFF_BF);
    {
        const uint32_t* whi = (const uint32_t*)g_whi;
        const uint32_t* wlo = (const uint32_t*)g_wlo;
#pragma unroll 4
        for (int i = 0; i < 64; i++) {
            int idx = tid + i * 128;
            int l = idx & 31, wq = (idx >> 5) & 3, sp = (idx >> 7) & 1, kt = idx >> 8;
            const uint32_t* src = sp ? wlo : whi;
            int gid = l >> 2, tig = l & 3;
            int kw = kt * 8 + tig;
            uint4 v;
            {
                int nl = (2 * wq) * 8 + gid;
                int grow = (nl & 3) * Hdim + j0 + (nl >> 2);
                v.x = src[grow * 256 + kw];
                v.y = src[grow * 256 + kw + 4];
            }
            {
                int nl = (2 * wq + 1) * 8 + gid;
                int grow = (nl & 3) * Hdim + j0 + (nl >> 2);
                v.z = src[grow * 256 + kw];
                v.w = src[grow * 256 + kw + 4];
            }
            BF4[idx] = v;
        }
    }

    const int mrow = (lane & 7) + ((lane >> 3) & 1) * 8;
    const int halfk = (lane >> 4) & 1;
    const uint32_t a_woff = (uint32_t)(mrow * 260 + halfk * 4);
    const uint32_t ahi = smem_u32(smw) + (OFF_HHI + a_woff) * 4;
    const uint32_t alo = smem_u32(smw) + (OFF_HLO + a_woff) * 4;

    __nv_bfloat16* hs_hi = (__nv_bfloat16*)(smw + OFF_HSHI);
    __nv_bfloat16* hs_lo = (__nv_bfloat16*)(smw + OFF_HSLO);
    float*         hs_f  = (float*)(smw + OFF_HSF);

    const int q = lane & 3, r = lane >> 2;
    const int b_loc = r + ((q & 1) << 3);
    const int q2 = q >> 1;
    const int bglob = b0 + b_loc;

    // staging decode for this thread (constant across steps):
    // idx = tid + i*128 spans 0..1023; sp = idx>>9, row = (idx&511)>>5, qq base = idx&31
    const uint32_t smem_base = smem_u32(smw);

    float c0 = 0.f, c1 = 0.f;
    __syncthreads();   // BF4 ready

    for (int t = 0; t < Tlen; t++) {
        const int cur = t & 1, nxt = cur ^ 1;

        // ---- 1. prefetch this thread's 8 pre scalars (overlaps the spin) ----
        float pr[2][4];
#pragma unroll
        for (int n8 = 0; n8 < 2; n8++) {
            const float* p = g_pre + ((size_t)t * Bsz + bglob) * G4H + j0 + w * 4 + n8 * 2 + q2;
#pragma unroll
            for (int g = 0; g < 4; g++) pr[n8][g] = __ldg(p + g * Hdim);
        }

        // ---- 2. wait for h_t (single spinner per block) ----
        if (t > 0) {
            if (tid == 0) {
                unsigned tgt = (unsigned)t * GBLK;
                while (ld_acquire(cnt) < tgt) { }
            }
            __syncthreads();
        }

        const uint4* shi = (const uint4*)g_hh[cur] + b0 * 64;
        const uint4* slo = (const uint4*)g_hl[cur] + b0 * 64;

        // ---- 3. cp.async staging: issue BOTH halves now, commit per half ----
#pragma unroll
        for (int i = 0; i < 8; i++) {              // half 0: words 0..31
            int idx = tid + i * 128;
            int sp = idx >> 9, rem = idx & 511;
            int row = rem >> 5, qq = rem & 31;
            const uint4* src = sp ? slo : shi;
            cp_async16(smem_base + ((sp ? OFF_HLO : OFF_HHI) + row * 260 + qq * 4) * 4,
                       src + row * 64 + qq);
        }
        cp_commit();
#pragma unroll
        for (int i = 0; i < 8; i++) {              // half 1: words 32..63
            int idx = tid + i * 128;
            int sp = idx >> 9, rem = idx & 511;
            int row = rem >> 5, qq = 32 + (rem & 31);
            const uint4* src = sp ? slo : shi;
            cp_async16(smem_base + ((sp ? OFF_HLO : OFF_HHI) + row * 260 + qq * 4) * 4,
                       src + row * 64 + qq);
        }
        cp_commit();

        cp_wait<1>();                               // half 0 landed
        __syncthreads();

        // ---- 4a. MMA K-half 0 (kt 0..15); half-1 copies complete underneath ----
        float d0[4] = {0.f, 0.f, 0.f, 0.f};
        float d1[4] = {0.f, 0.f, 0.f, 0.f};
#pragma unroll 8
        for (int kt = 0; kt < 16; kt++) {
            uint32_t ah[4], al[4];
            ldsm4(ah, ahi + kt * 32);
            ldsm4(al, alo + kt * 32);
            uint4 bh = BF4[((kt * 2 + 0) * 4 + w) * 32 + lane];
            uint4 bl = BF4[((kt * 2 + 1) * 4 + w) * 32 + lane];
            mma16816(d0, ah, bh.x, bh.y);
            mma16816(d0, ah, bl.x, bl.y);
            mma16816(d0, al, bh.x, bh.y);
            mma16816(d1, ah, bh.z, bh.w);
            mma16816(d1, ah, bl.z, bl.w);
            mma16816(d1, al, bh.z, bh.w);
        }

        cp_wait<0>();                               // half 1 landed
        __syncthreads();

        // ---- 4b. MMA K-half 1 (kt 16..31) ----
#pragma unroll 8
        for (int kt = 16; kt < 32; kt++) {
            uint32_t ah[4], al[4];
            ldsm4(ah, ahi + kt * 32);
            ldsm4(al, alo + kt * 32);
            uint4 bh = BF4[((kt * 2 + 0) * 4 + w) * 32 + lane];
            uint4 bl = BF4[((kt * 2 + 1) * 4 + w) * 32 + lane];
            mma16816(d0, ah, bh.x, bh.y);
            mma16816(d0, ah, bl.x, bl.y);
            mma16816(d0, al, bh.x, bh.y);
            mma16816(d1, ah, bh.z, bh.w);
            mma16816(d1, ah, bl.z, bl.w);
            mma16816(d1, al, bh.z, bh.w);
        }

        // ---- 5. epilogue: compute cells, stage h/hi/lo into smem ----
#pragma unroll
        for (int n8 = 0; n8 < 2; n8++) {
            float* dd = n8 ? d1 : d0;
            float e0 = __shfl_xor_sync(0xffffffffu, dd[0], 1);
            float e1 = __shfl_xor_sync(0xffffffffu, dd[1], 1);
            float e2 = __shfl_xor_sync(0xffffffffu, dd[2], 1);
            float e3 = __shfl_xor_sync(0xffffffffu, dd[3], 1);
            float ai, af, ag, ao;
            if ((q & 1) == 0) { ai = dd[0]; af = dd[1]; ag = e0;    ao = e1;    }
            else              { ai = e2;    af = e3;    ag = dd[2]; ao = dd[3]; }
            ai += pr[n8][0]; af += pr[n8][1]; ag += pr[n8][2]; ao += pr[n8][3];

            float ig = fast_sigmoid(ai);
            float fg = fast_sigmoid(af);
            float gg = fast_tanh(ag);
            float og = fast_sigmoid(ao);
            float& c = n8 ? c1 : c0;
            c = fg * c + ig * gg;
            float h = og * fast_tanh(c);

            int ub = w * 4 + n8 * 2 + q2;                  // unit within block
            __nv_bfloat16 hhv = __float2bfloat16(h);
            hs_hi[b_loc * 16 + ub] = hhv;
            hs_lo[b_loc * 16 + ub] = __float2bfloat16(h - __bfloat162float(hhv));
            hs_f [b_loc * 16 + ub] = h;
            if (t == Tlen - 1) cn[(size_t)bglob * Hdim + j0 + ub] = c;
        }
        __syncthreads();   // hs_* ready

        // ---- 6. coalesced critical stores: h split (64 x uint4) ----
        if (tid < 64) {
            int row = (tid & 31) >> 1, qq = tid & 1;
            if (tid < 32) {
                uint4 v = ((const uint4*)hs_hi)[tid];
                *((uint4*)(g_hh[nxt] + (size_t)(b0 + row) * Hdim + j0) + qq) = v;
            } else {
                uint4 v = ((const uint4*)hs_lo)[tid - 32];
                *((uint4*)(g_hl[nxt] + (size_t)(b0 + row) * Hdim + j0) + qq) = v;
            }
        }
        __syncthreads();   // h-split stores performed block-wide

        // ---- 7. release (single arriver) ----
        if (t < Tlen - 1 && tid == 0) red_release_add(cnt);

        // ---- 8. off-critical-path coalesced out rows (+hn at the end) ----
        {
            int row = tid >> 3, k2 = tid & 7;
            float2 v = ((const float2*)hs_f)[tid];
            *(float2*)(out + (size_t)(b0 + row) * Tlen * Hdim + (size_t)t * Hdim
                       + j0 + k2 * 2) = v;
            if (t == Tlen - 1)
                *(float2*)(hn + (size_t)(b0 + row) * Hdim + j0 + k2 * 2) = v;
        }
    }
}

// ---------------- launch ----------------
extern "C" void kernel_launch(void* const* d_in, const int* in_sizes, int n_in,
                              void* d_out, int out_size) {
    const float* x    = (const float*)d_in[0];
    const float* w_ih = (const float*)d_in[1];
    const float* w_hh = (const float*)d_in[2];
    const float* b_ih = (const float*)d_in[3];
    const float* b_hh = (const float*)d_in[4];

    float* out = (float*)d_out;
    float* hn  = out + (size_t)Bsz * Tlen * Hdim;
    float* cn  = hn + (size_t)Bsz * Hdim;

    static const size_t GEMM_SMEM = 4 * TILE_W * sizeof(uint32_t);
    static const size_t SCAN_SMEM = SCAN_WORDS * sizeof(uint32_t);   // 166400 B
    cudaFuncSetAttribute(gemm_pre, cudaFuncAttributeMaxDynamicSharedMemorySize,
                         (int)GEMM_SMEM);
    cudaFuncSetAttribute(lstm_scan, cudaFuncAttributeMaxDynamicSharedMemorySize,
                         (int)SCAN_SMEM);

    prep_kernel<<<(Bsz * Tlen * Idim) / 256, 256>>>(x, w_ih, w_hh);
    gemm_pre<<<dim3(G4H / 128, (Bsz * Tlen) / 128), 256, GEMM_SMEM>>>(b_ih, b_hh);
    lstm_scan<<<NBLK, 128, SCAN_SMEM>>>(out, hn, cn);
}

// round 12
// speedup vs baseline: 1.0252x; 1.0252x over previous
#include <cuda_runtime.h>
#include <cuda_bf16.h>
#include <cstdint>

#define Bsz 64
#define Tlen 1024
#define Idim 256
#define Hdim 512
#define G4H  2048
#define NBLK 128
#define NGRP 4            // independent batch groups
#define GBLK 32           // unit-blocks per group

// ---------------- device scratch ----------------
__device__ float          g_pre[(size_t)Bsz * Tlen * G4H];   // [T][B][4H]
__device__ __nv_bfloat16  g_whi[G4H * Hdim];                 // w_hh split
__device__ __nv_bfloat16  g_wlo[G4H * Hdim];
__device__ __nv_bfloat16  g_wihi[G4H * Idim];                // w_ih split
__device__ __nv_bfloat16  g_wilo[G4H * Idim];
__device__ __nv_bfloat16  g_xhi[(size_t)Bsz * Tlen * Idim];  // x split
__device__ __nv_bfloat16  g_xlo[(size_t)Bsz * Tlen * Idim];
__device__ __nv_bfloat16  g_hh[2][Bsz * Hdim];
__device__ __nv_bfloat16  g_hl[2][Bsz * Hdim];
__device__ unsigned       g_cnt[NGRP * 32];                  // per-group counters, 128B apart

// ---------------- helpers ----------------
__device__ __forceinline__ uint32_t smem_u32(const void* p) {
    uint32_t a;
    asm("{ .reg .u64 t; cvta.to.shared.u64 t, %1; cvt.u32.u64 %0, t; }" : "=r"(a) : "l"(p));
    return a;
}
__device__ __forceinline__ void ldsm4(uint32_t (&r)[4], uint32_t addr) {
    asm volatile("ldmatrix.sync.aligned.m8n8.x4.shared.b16 {%0,%1,%2,%3}, [%4];"
                 : "=r"(r[0]), "=r"(r[1]), "=r"(r[2]), "=r"(r[3]) : "r"(addr));
}
__device__ __forceinline__ void mma16816(float (&d)[4], const uint32_t (&a)[4],
                                         uint32_t b0, uint32_t b1) {
    asm volatile("mma.sync.aligned.m16n8k16.row.col.f32.bf16.bf16.f32 "
                 "{%0,%1,%2,%3}, {%4,%5,%6,%7}, {%8,%9}, {%0,%1,%2,%3};"
                 : "+f"(d[0]), "+f"(d[1]), "+f"(d[2]), "+f"(d[3])
                 : "r"(a[0]), "r"(a[1]), "r"(a[2]), "r"(a[3]), "r"(b0), "r"(b1));
}
__device__ __forceinline__ void split1(float v, __nv_bfloat16* hi, __nv_bfloat16* lo) {
    __nv_bfloat16 h = __float2bfloat16(v);
    *hi = h;
    *lo = __float2bfloat16(v - __bfloat162float(h));
}
__device__ __forceinline__ void red_release_add(unsigned* p) {
    asm volatile("red.release.gpu.global.add.u32 [%0], 1;" :: "l"(p) : "memory");
}
__device__ __forceinline__ unsigned ld_acquire(const unsigned* p) {
    unsigned v;
    asm volatile("ld.acquire.gpu.global.u32 %0, [%1];" : "=r"(v) : "l"(p) : "memory");
    return v;
}
__device__ __forceinline__ float fast_sigmoid(float x) {
    return __fdividef(1.f, 1.f + __expf(-x));
}
__device__ __forceinline__ float fast_tanh(float x) {
    return 1.f - __fdividef(2.f, __expf(2.f * x) + 1.f);
}

// ---------------- ncu slot probes (diagnostic no-ops) ----------------
__global__ void probe_a() {}
__global__ void probe_b() {}
__global__ void probe_c() {}

// ---------------- prologue ----------------
__global__ void prep_kernel(const float* __restrict__ x,
                            const float* __restrict__ w_ih,
                            const float* __restrict__ w_hh) {
    int idx = blockIdx.x * blockDim.x + threadIdx.x;
    if (idx < NGRP * 32) g_cnt[idx] = 0u;
    if (idx < 16384) {
        ((uint32_t*)g_hh[0])[idx] = 0u;
        ((uint32_t*)g_hl[0])[idx] = 0u;
    }
    if (idx < G4H * Hdim) split1(w_hh[idx], g_whi + idx, g_wlo + idx);
    if (idx < G4H * Idim) split1(w_ih[idx], g_wihi + idx, g_wilo + idx);
    split1(x[idx], g_xhi + idx, g_xlo + idx);
}

// ---------------- Kernel A: tensor-core pre-GEMM (unchanged, proven) ----------------
#define GS 36
#define TILE_W (128 * GS)
__global__ void __launch_bounds__(256) gemm_pre(const float* __restrict__ bih,
                                                const float* __restrict__ bhh) {
    extern __shared__ uint32_t sm[];
    uint32_t* xs_hi = sm;
    uint32_t* xs_lo = sm + TILE_W;
    uint32_t* ws_hi = sm + 2 * TILE_W;
    uint32_t* ws_lo = sm + 3 * TILE_W;

    const int tid = threadIdx.x;
    const int lane = tid & 31, wid = tid >> 5;
    const int wm = wid & 1, wn = wid >> 1;
    const int m0 = blockIdx.y * 128;
    const int n0 = blockIdx.x * 128;

    const uint32_t a_off = (uint32_t)(((lane & 7) + ((lane >> 3) & 1) * 8) * GS
                                      + ((lane >> 4) & 1) * 4);
    const uint32_t b_off = (uint32_t)((((lane >> 4) & 1) * 8 + (lane & 7)) * GS
                                      + ((lane >> 3) & 1) * 4);
    const uint32_t axh = smem_u32(xs_hi) + (a_off + (wm * 64) * GS) * 4;
    const uint32_t axl = smem_u32(xs_lo) + (a_off + (wm * 64) * GS) * 4;
    const uint32_t bwh = smem_u32(ws_hi) + (b_off + (wn * 32) * GS) * 4;
    const uint32_t bwl = smem_u32(ws_lo) + (b_off + (wn * 32) * GS) * 4;

    float d[4][4][4];
#pragma unroll
    for (int i = 0; i < 4; i++)
#pragma unroll
        for (int j = 0; j < 4; j++)
#pragma unroll
            for (int r = 0; r < 4; r++) d[i][j][r] = 0.f;

    for (int kc = 0; kc < Idim / 64; kc++) {
#pragma unroll
        for (int i = 0; i < 4; i++) {
            int idx = tid + i * 256;
            int row = idx >> 3, q = idx & 7;
            uint32_t dst = row * GS + q * 4;
            *(uint4*)(xs_hi + dst) = *((const uint4*)(g_xhi + (size_t)(m0 + row) * Idim + kc * 64) + q);
            *(uint4*)(xs_lo + dst) = *((const uint4*)(g_xlo + (size_t)(m0 + row) * Idim + kc * 64) + q);
            *(uint4*)(ws_hi + dst) = *((const uint4*)(g_wihi + (size_t)(n0 + row) * Idim + kc * 64) + q);
            *(uint4*)(ws_lo + dst) = *((const uint4*)(g_wilo + (size_t)(n0 + row) * Idim + kc * 64) + q);
        }
        __syncthreads();

#pragma unroll
        for (int kt = 0; kt < 4; kt++) {
            uint32_t ah[4][4], al[4][4];
#pragma unroll
            for (int mi = 0; mi < 4; mi++) {
                uint32_t o = (mi * 16 * GS + kt * 8) * 4;
                ldsm4(ah[mi], axh + o);
                ldsm4(al[mi], axl + o);
            }
            uint2 bh[4], bl[4];
#pragma unroll
            for (int ni = 0; ni < 2; ni++) {
                uint32_t o = (ni * 16 * GS + kt * 8) * 4;
                uint32_t th[4], tl[4];
                ldsm4(th, bwh + o);
                ldsm4(tl, bwl + o);
                bh[ni * 2]     = make_uint2(th[0], th[1]);
                bh[ni * 2 + 1] = make_uint2(th[2], th[3]);
                bl[ni * 2]     = make_uint2(tl[0], tl[1]);
                bl[ni * 2 + 1] = make_uint2(tl[2], tl[3]);
            }
#pragma unroll
            for (int mi = 0; mi < 4; mi++)
#pragma unroll
                for (int n8 = 0; n8 < 4; n8++) {
                    mma16816(d[mi][n8], ah[mi], bh[n8].x, bh[n8].y);
                    mma16816(d[mi][n8], ah[mi], bl[n8].x, bl[n8].y);
                    mma16816(d[mi][n8], al[mi], bh[n8].x, bh[n8].y);
                }
        }
        __syncthreads();
    }

#pragma unroll
    for (int n8 = 0; n8 < 4; n8++) {
        int col = n0 + wn * 32 + n8 * 8 + (lane & 3) * 2;
        float bx = __ldg(bih + col) + __ldg(bhh + col);
        float by = __ldg(bih + col + 1) + __ldg(bhh + col + 1);
#pragma unroll
        for (int mi = 0; mi < 4; mi++) {
            int row0 = m0 + wm * 64 + mi * 16 + (lane >> 2);
            int row1 = row0 + 8;
            size_t dr0 = ((size_t)(row0 & (Tlen - 1)) * Bsz + (row0 >> 10)) * G4H;
            size_t dr1 = ((size_t)(row1 & (Tlen - 1)) * Bsz + (row1 >> 10)) * G4H;
            *(float2*)(g_pre + dr0 + col) = make_float2(d[mi][n8][0] + bx, d[mi][n8][1] + by);
            *(float2*)(g_pre + dr1 + col) = make_float2(d[mi][n8][2] + bx, d[mi][n8][3] + by);
        }
    }
}

// ---------------- Kernel B: batch-sharded persistent scan ----------------
// R10 staging (LDG->reg->STS pipelined K-halves) + B fragments for kt 0..15
// held in registers for the whole t-loop (halves BF4 crossbar traffic).
#define OFF_HHI   0                     // 16 rows x 260 words
#define OFF_HLO   4160
#define OFF_BF    8320                  // 8192 uint4 = 32768 words
#define OFF_HSHI  41088                 // 16x16 bf16 = 128 words
#define OFF_HSLO  41216                 // 128 words
#define OFF_HSF   41344                 // 16x16 f32 = 256 words
#define SCAN_WORDS 41600                // 166400 bytes

__global__ void __launch_bounds__(128) lstm_scan(float* __restrict__ out,
                                                 float* __restrict__ hn,
                                                 float* __restrict__ cn) {
    extern __shared__ uint32_t smw[];
    const int tid = threadIdx.x;
    const int lane = tid & 31, w = tid >> 5;
    const int bg = blockIdx.x >> 5, ug = blockIdx.x & 31;
    const int j0 = ug * 16, b0 = bg * 16;
    unsigned* cnt = &g_cnt[bg * 32];

    // ---- fill B fragments once (validated) ----
    uint4* BF4 = (uint4*)(smw + OFF_BF);
    {
        const uint32_t* whi = (const uint32_t*)g_whi;
        const uint32_t* wlo = (const uint32_t*)g_wlo;
#pragma unroll 4
        for (int i = 0; i < 64; i++) {
            int idx = tid + i * 128;
            int l = idx & 31, wq = (idx >> 5) & 3, sp = (idx >> 7) & 1, kt = idx >> 8;
            const uint32_t* src = sp ? wlo : whi;
            int gid = l >> 2, tig = l & 3;
            int kw = kt * 8 + tig;
            uint4 v;
            {
                int nl = (2 * wq) * 8 + gid;
                int grow = (nl & 3) * Hdim + j0 + (nl >> 2);
                v.x = src[grow * 256 + kw];
                v.y = src[grow * 256 + kw + 4];
            }
            {
                int nl = (2 * wq + 1) * 8 + gid;
                int grow = (nl & 3) * Hdim + j0 + (nl >> 2);
                v.z = src[grow * 256 + kw];
                v.w = src[grow * 256 + kw + 4];
            }
            BF4[idx] = v;
        }
    }

    const int mrow = (lane & 7) + ((lane >> 3) & 1) * 8;
    const int halfk = (lane >> 4) & 1;
    const uint32_t a_woff = (uint32_t)(mrow * 260 + halfk * 4);
    const uint32_t ahi = smem_u32(smw) + (OFF_HHI + a_woff) * 4;
    const uint32_t alo = smem_u32(smw) + (OFF_HLO + a_woff) * 4;

    __nv_bfloat16* hs_hi = (__nv_bfloat16*)(smw + OFF_HSHI);
    __nv_bfloat16* hs_lo = (__nv_bfloat16*)(smw + OFF_HSLO);
    float*         hs_f  = (float*)(smw + OFF_HSF);

    const int q = lane & 3, r = lane >> 2;
    const int b_loc = r + ((q & 1) << 3);
    const int q2 = q >> 1;
    const int bglob = b0 + b_loc;

    float c0 = 0.f, c1 = 0.f;
    __syncthreads();   // BF4 ready

    // ---- hoist kt 0..15 B fragments into registers (loop-invariant) ----
    uint4 Brh[16], Brl[16];
#pragma unroll
    for (int kt = 0; kt < 16; kt++) {
        Brh[kt] = BF4[((kt * 2 + 0) * 4 + w) * 32 + lane];
        Brl[kt] = BF4[((kt * 2 + 1) * 4 + w) * 32 + lane];
    }

    for (int t = 0; t < Tlen; t++) {
        const int cur = t & 1, nxt = cur ^ 1;

        // ---- 1. prefetch this thread's 8 pre scalars (overlaps the spin) ----
        float pr[2][4];
#pragma unroll
        for (int n8 = 0; n8 < 2; n8++) {
            const float* p = g_pre + ((size_t)t * Bsz + bglob) * G4H + j0 + w * 4 + n8 * 2 + q2;
#pragma unroll
            for (int g = 0; g < 4; g++) pr[n8][g] = __ldg(p + g * Hdim);
        }

        // ---- 2. wait for h_t (single spinner per block) ----
        if (t > 0) {
            if (tid == 0) {
                unsigned tgt = (unsigned)t * GBLK;
                while (ld_acquire(cnt) < tgt) { }
            }
            __syncthreads();
        }

        const uint4* shi = (const uint4*)g_hh[cur] + b0 * 64;
        const uint4* slo = (const uint4*)g_hl[cur] + b0 * 64;

        // ---- 3a. stage K-half 0 (words q 0..31, both splits) ----
#pragma unroll
        for (int i = 0; i < 8; i++) {
            int idx = tid + i * 128;                 // 0..1023
            int sp = idx >> 9, rem = idx & 511;
            int row = rem >> 5, qq = rem & 31;
            const uint4* src = sp ? slo : shi;
            uint4 v = __ldcg(src + row * 64 + qq);
            *(uint4*)(smw + (sp ? OFF_HLO : OFF_HHI) + row * 260 + qq * 4) = v;
        }
        __syncthreads();

        // ---- 3b. issue K-half 1 LDGs into registers (completes under MMA) ----
        uint4 hbuf[8];
#pragma unroll
        for (int i = 0; i < 8; i++) {
            int idx = tid + i * 128;
            int sp = idx >> 9, rem = idx & 511;
            int row = rem >> 5, qq = 32 + (rem & 31);
            const uint4* src = sp ? slo : shi;
            hbuf[i] = __ldcg(src + row * 64 + qq);
        }

        // ---- 4a. MMA K-half 0 (kt 0..15) with register-resident B ----
        float d0[4] = {0.f, 0.f, 0.f, 0.f};
        float d1[4] = {0.f, 0.f, 0.f, 0.f};
#pragma unroll
        for (int kt = 0; kt < 16; kt++) {
            uint32_t ah[4], al[4];
            ldsm4(ah, ahi + kt * 32);
            ldsm4(al, alo + kt * 32);
            mma16816(d0, ah, Brh[kt].x, Brh[kt].y);
            mma16816(d0, ah, Brl[kt].x, Brl[kt].y);
            mma16816(d0, al, Brh[kt].x, Brh[kt].y);
            mma16816(d1, ah, Brh[kt].z, Brh[kt].w);
            mma16816(d1, ah, Brl[kt].z, Brl[kt].w);
            mma16816(d1, al, Brh[kt].z, Brh[kt].w);
        }

        // ---- 4b. commit K-half 1 to smem, sync, MMA (kt 16..31) from BF4 ----
#pragma unroll
        for (int i = 0; i < 8; i++) {
            int idx = tid + i * 128;
            int sp = idx >> 9, rem = idx & 511;
            int row = rem >> 5, qq = 32 + (rem & 31);
            *(uint4*)(smw + (sp ? OFF_HLO : OFF_HHI) + row * 260 + qq * 4) = hbuf[i];
        }
        __syncthreads();

#pragma unroll 8
        for (int kt = 16; kt < 32; kt++) {
            uint32_t ah[4], al[4];
            ldsm4(ah, ahi + kt * 32);
            ldsm4(al, alo + kt * 32);
            uint4 bh = BF4[((kt * 2 + 0) * 4 + w) * 32 + lane];
            uint4 bl = BF4[((kt * 2 + 1) * 4 + w) * 32 + lane];
            mma16816(d0, ah, bh.x, bh.y);
            mma16816(d0, ah, bl.x, bl.y);
            mma16816(d0, al, bh.x, bh.y);
            mma16816(d1, ah, bh.z, bh.w);
            mma16816(d1, ah, bl.z, bl.w);
            mma16816(d1, al, bh.z, bh.w);
        }

        // ---- 5. epilogue: compute cells, stage h/hi/lo into smem ----
#pragma unroll
        for (int n8 = 0; n8 < 2; n8++) {
            float* dd = n8 ? d1 : d0;
            float e0 = __shfl_xor_sync(0xffffffffu, dd[0], 1);
            float e1 = __shfl_xor_sync(0xffffffffu, dd[1], 1);
            float e2 = __shfl_xor_sync(0xffffffffu, dd[2], 1);
            float e3 = __shfl_xor_sync(0xffffffffu, dd[3], 1);
            float ai, af, ag, ao;
            if ((q & 1) == 0) { ai = dd[0]; af = dd[1]; ag = e0;    ao = e1;    }
            else              { ai = e2;    af = e3;    ag = dd[2]; ao = dd[3]; }
            ai += pr[n8][0]; af += pr[n8][1]; ag += pr[n8][2]; ao += pr[n8][3];

            float ig = fast_sigmoid(ai);
            float fg = fast_sigmoid(af);
            float gg = fast_tanh(ag);
            float og = fast_sigmoid(ao);
            float& c = n8 ? c1 : c0;
            c = fg * c + ig * gg;
            float h = og * fast_tanh(c);

            int ub = w * 4 + n8 * 2 + q2;                  // unit within block
            __nv_bfloat16 hhv = __float2bfloat16(h);
            hs_hi[b_loc * 16 + ub] = hhv;
            hs_lo[b_loc * 16 + ub] = __float2bfloat16(h - __bfloat162float(hhv));
            hs_f [b_loc * 16 + ub] = h;
            if (t == Tlen - 1) cn[(size_t)bglob * Hdim + j0 + ub] = c;
        }
        __syncthreads();   // hs_* ready

        // ---- 6. coalesced critical stores: h split (64 x uint4) ----
        if (tid < 64) {
            int row = (tid & 31) >> 1, qq = tid & 1;
            if (tid < 32) {
                uint4 v = ((const uint4*)hs_hi)[tid];
                *((uint4*)(g_hh[nxt] + (size_t)(b0 + row) * Hdim + j0) + qq) = v;
            } else {
                uint4 v = ((const uint4*)hs_lo)[tid - 32];
                *((uint4*)(g_hl[nxt] + (size_t)(b0 + row) * Hdim + j0) + qq) = v;
            }
        }
        __syncthreads();   // h-split stores performed block-wide

        // ---- 7. release (single arriver) ----
        if (t < Tlen - 1 && tid == 0) red_release_add(cnt);

        // ---- 8. off-critical-path coalesced out rows (+hn at the end) ----
        {
            int row = tid >> 3, k2 = tid & 7;
            float2 v = ((const float2*)hs_f)[tid];
            *(float2*)(out + (size_t)(b0 + row) * Tlen * Hdim + (size_t)t * Hdim
                       + j0 + k2 * 2) = v;
            if (t == Tlen - 1)
                *(float2*)(hn + (size_t)(b0 + row) * Hdim + j0 + k2 * 2) = v;
        }
    }
}

// ---------------- launch ----------------
extern "C" void kernel_launch(void* const* d_in, const int* in_sizes, int n_in,
                              void* d_out, int out_size) {
    const float* x    = (const float*)d_in[0];
    const float* w_ih = (const float*)d_in[1];
    const float* w_hh = (const float*)d_in[2];
    const float* b_ih = (const float*)d_in[3];
    const float* b_hh = (const float*)d_in[4];

    float* out = (float*)d_out;
    float* hn  = out + (size_t)Bsz * Tlen * Hdim;
    float* cn  = hn + (size_t)Bsz * Hdim;

    static const size_t GEMM_SMEM = 4 * TILE_W * sizeof(uint32_t);
    static const size_t SCAN_SMEM = SCAN_WORDS * sizeof(uint32_t);   // 166400 B
    cudaFuncSetAttribute(gemm_pre, cudaFuncAttributeMaxDynamicSharedMemorySize,
                         (int)GEMM_SMEM);
    cudaFuncSetAttribute(lstm_scan, cudaFuncAttributeMaxDynamicSharedMemorySize,
                         (int)SCAN_SMEM);

    // probes shift lstm_scan to launch index 5 for the ncu -s 5 -c 1 capture
    prep_kernel<<<(Bsz * Tlen * Idim) / 256, 256>>>(x, w_ih, w_hh);
    probe_a<<<1, 32>>>();
    probe_b<<<1, 32>>>();
    probe_c<<<1, 32>>>();
    gemm_pre<<<dim3(G4H / 128, (Bsz * Tlen) / 128), 256, GEMM_SMEM>>>(b_ih, b_hh);
    lstm_scan<<<NBLK, 128, SCAN_SMEM>>>(out, hn, cn);
}

// round 13
// speedup vs baseline: 1.0629x; 1.0368x over previous
#include <cuda_runtime.h>
#include <cuda_bf16.h>
#include <cstdint>

#define Bsz 64
#define Tlen 1024
#define Idim 256
#define Hdim 512
#define G4H  2048
#define NBLK 128
#define NGRP 4            // independent batch groups
#define GBLK 32           // unit-blocks per group

// ---------------- device scratch ----------------
__device__ float          g_pre[(size_t)Bsz * Tlen * G4H];   // [T][B][4H]
__device__ __nv_bfloat16  g_whi[G4H * Hdim];                 // w_hh split
__device__ __nv_bfloat16  g_wlo[G4H * Hdim];
__device__ __nv_bfloat16  g_wihi[G4H * Idim];                // w_ih split
__device__ __nv_bfloat16  g_wilo[G4H * Idim];
__device__ __nv_bfloat16  g_xhi[(size_t)Bsz * Tlen * Idim];  // x split
__device__ __nv_bfloat16  g_xlo[(size_t)Bsz * Tlen * Idim];
__device__ __nv_bfloat16  g_hh[2][Bsz * Hdim];
__device__ __nv_bfloat16  g_hl[2][Bsz * Hdim];
__device__ unsigned       g_cnt[NGRP * 32];                  // per-group counters, 128B apart

// ---------------- helpers ----------------
__device__ __forceinline__ uint32_t smem_u32(const void* p) {
    uint32_t a;
    asm("{ .reg .u64 t; cvta.to.shared.u64 t, %1; cvt.u32.u64 %0, t; }" : "=r"(a) : "l"(p));
    return a;
}
__device__ __forceinline__ void ldsm4(uint32_t (&r)[4], uint32_t addr) {
    asm volatile("ldmatrix.sync.aligned.m8n8.x4.shared.b16 {%0,%1,%2,%3}, [%4];"
                 : "=r"(r[0]), "=r"(r[1]), "=r"(r[2]), "=r"(r[3]) : "r"(addr));
}
__device__ __forceinline__ void mma16816(float (&d)[4], const uint32_t (&a)[4],
                                         uint32_t b0, uint32_t b1) {
    asm volatile("mma.sync.aligned.m16n8k16.row.col.f32.bf16.bf16.f32 "
                 "{%0,%1,%2,%3}, {%4,%5,%6,%7}, {%8,%9}, {%0,%1,%2,%3};"
                 : "+f"(d[0]), "+f"(d[1]), "+f"(d[2]), "+f"(d[3])
                 : "r"(a[0]), "r"(a[1]), "r"(a[2]), "r"(a[3]), "r"(b0), "r"(b1));
}
__device__ __forceinline__ void split1(float v, __nv_bfloat16* hi, __nv_bfloat16* lo) {
    __nv_bfloat16 h = __float2bfloat16(v);
    *hi = h;
    *lo = __float2bfloat16(v - __bfloat162float(h));
}
__device__ __forceinline__ void red_release_add(unsigned* p) {
    asm volatile("red.release.gpu.global.add.u32 [%0], 1;" :: "l"(p) : "memory");
}
__device__ __forceinline__ unsigned ld_acquire(const unsigned* p) {
    unsigned v;
    asm volatile("ld.acquire.gpu.global.u32 %0, [%1];" : "=r"(v) : "l"(p) : "memory");
    return v;
}
__device__ __forceinline__ float fast_sigmoid(float x) {
    return __fdividef(1.f, 1.f + __expf(-x));
}
__device__ __forceinline__ float fast_tanh(float x) {
    return 1.f - __fdividef(2.f, __expf(2.f * x) + 1.f);
}

// ---------------- ncu slot probe (capture lands on user launch index 3) ----------------
__global__ void probe_a() {}

// ---------------- prologue ----------------
__global__ void prep_kernel(const float* __restrict__ x,
                            const float* __restrict__ w_ih,
                            const float* __restrict__ w_hh) {
    int idx = blockIdx.x * blockDim.x + threadIdx.x;
    if (idx < NGRP * 32) g_cnt[idx] = 0u;
    if (idx < 16384) {
        ((uint32_t*)g_hh[0])[idx] = 0u;
        ((uint32_t*)g_hl[0])[idx] = 0u;
    }
    if (idx < G4H * Hdim) split1(w_hh[idx], g_whi + idx, g_wlo + idx);
    if (idx < G4H * Idim) split1(w_ih[idx], g_wihi + idx, g_wilo + idx);
    split1(x[idx], g_xhi + idx, g_xlo + idx);
}

// ---------------- Kernel A: tensor-core pre-GEMM (unchanged, proven) ----------------
#define GS 36
#define TILE_W (128 * GS)
__global__ void __launch_bounds__(256) gemm_pre(const float* __restrict__ bih,
                                                const float* __restrict__ bhh) {
    extern __shared__ uint32_t sm[];
    uint32_t* xs_hi = sm;
    uint32_t* xs_lo = sm + TILE_W;
    uint32_t* ws_hi = sm + 2 * TILE_W;
    uint32_t* ws_lo = sm + 3 * TILE_W;

    const int tid = threadIdx.x;
    const int lane = tid & 31, wid = tid >> 5;
    const int wm = wid & 1, wn = wid >> 1;
    const int m0 = blockIdx.y * 128;
    const int n0 = blockIdx.x * 128;

    const uint32_t a_off = (uint32_t)(((lane & 7) + ((lane >> 3) & 1) * 8) * GS
                                      + ((lane >> 4) & 1) * 4);
    const uint32_t b_off = (uint32_t)((((lane >> 4) & 1) * 8 + (lane & 7)) * GS
                                      + ((lane >> 3) & 1) * 4);
    const uint32_t axh = smem_u32(xs_hi) + (a_off + (wm * 64) * GS) * 4;
    const uint32_t axl = smem_u32(xs_lo) + (a_off + (wm * 64) * GS) * 4;
    const uint32_t bwh = smem_u32(ws_hi) + (b_off + (wn * 32) * GS) * 4;
    const uint32_t bwl = smem_u32(ws_lo) + (b_off + (wn * 32) * GS) * 4;

    float d[4][4][4];
#pragma unroll
    for (int i = 0; i < 4; i++)
#pragma unroll
        for (int j = 0; j < 4; j++)
#pragma unroll
            for (int r = 0; r < 4; r++) d[i][j][r] = 0.f;

    for (int kc = 0; kc < Idim / 64; kc++) {
#pragma unroll
        for (int i = 0; i < 4; i++) {
            int idx = tid + i * 256;
            int row = idx >> 3, q = idx & 7;
            uint32_t dst = row * GS + q * 4;
            *(uint4*)(xs_hi + dst) = *((const uint4*)(g_xhi + (size_t)(m0 + row) * Idim + kc * 64) + q);
            *(uint4*)(xs_lo + dst) = *((const uint4*)(g_xlo + (size_t)(m0 + row) * Idim + kc * 64) + q);
            *(uint4*)(ws_hi + dst) = *((const uint4*)(g_wihi + (size_t)(n0 + row) * Idim + kc * 64) + q);
            *(uint4*)(ws_lo + dst) = *((const uint4*)(g_wilo + (size_t)(n0 + row) * Idim + kc * 64) + q);
        }
        __syncthreads();

#pragma unroll
        for (int kt = 0; kt < 4; kt++) {
            uint32_t ah[4][4], al[4][4];
#pragma unroll
            for (int mi = 0; mi < 4; mi++) {
                uint32_t o = (mi * 16 * GS + kt * 8) * 4;
                ldsm4(ah[mi], axh + o);
                ldsm4(al[mi], axl + o);
            }
            uint2 bh[4], bl[4];
#pragma unroll
            for (int ni = 0; ni < 2; ni++) {
                uint32_t o = (ni * 16 * GS + kt * 8) * 4;
                uint32_t th[4], tl[4];
                ldsm4(th, bwh + o);
                ldsm4(tl, bwl + o);
                bh[ni * 2]     = make_uint2(th[0], th[1]);
                bh[ni * 2 + 1] = make_uint2(th[2], th[3]);
                bl[ni * 2]     = make_uint2(tl[0], tl[1]);
                bl[ni * 2 + 1] = make_uint2(tl[2], tl[3]);
            }
#pragma unroll
            for (int mi = 0; mi < 4; mi++)
#pragma unroll
                for (int n8 = 0; n8 < 4; n8++) {
                    mma16816(d[mi][n8], ah[mi], bh[n8].x, bh[n8].y);
                    mma16816(d[mi][n8], ah[mi], bl[n8].x, bl[n8].y);
                    mma16816(d[mi][n8], al[mi], bh[n8].x, bh[n8].y);
                }
        }
        __syncthreads();
    }

#pragma unroll
    for (int n8 = 0; n8 < 4; n8++) {
        int col = n0 + wn * 32 + n8 * 8 + (lane & 3) * 2;
        float bx = __ldg(bih + col) + __ldg(bhh + col);
        float by = __ldg(bih + col + 1) + __ldg(bhh + col + 1);
#pragma unroll
        for (int mi = 0; mi < 4; mi++) {
            int row0 = m0 + wm * 64 + mi * 16 + (lane >> 2);
            int row1 = row0 + 8;
            size_t dr0 = ((size_t)(row0 & (Tlen - 1)) * Bsz + (row0 >> 10)) * G4H;
            size_t dr1 = ((size_t)(row1 & (Tlen - 1)) * Bsz + (row1 >> 10)) * G4H;
            *(float2*)(g_pre + dr0 + col) = make_float2(d[mi][n8][0] + bx, d[mi][n8][1] + by);
            *(float2*)(g_pre + dr1 + col) = make_float2(d[mi][n8][2] + bx, d[mi][n8][3] + by);
        }
    }
}

// ---------------- Kernel B: batch-sharded persistent scan (R12-pass, unchanged) ----------------
#define OFF_HHI   0                     // 16 rows x 260 words
#define OFF_HLO   4160
#define OFF_BF    8320                  // 8192 uint4 = 32768 words
#define OFF_HSHI  41088                 // 16x16 bf16 = 128 words
#define OFF_HSLO  41216                 // 128 words
#define OFF_HSF   41344                 // 16x16 f32 = 256 words
#define SCAN_WORDS 41600                // 166400 bytes

__global__ void __launch_bounds__(128) lstm_scan(float* __restrict__ out,
                                                 float* __restrict__ hn,
                                                 float* __restrict__ cn) {
    extern __shared__ uint32_t smw[];
    const int tid = threadIdx.x;
    const int lane = tid & 31, w = tid >> 5;
    const int bg = blockIdx.x >> 5, ug = blockIdx.x & 31;
    const int j0 = ug * 16, b0 = bg * 16;
    unsigned* cnt = &g_cnt[bg * 32];

    // ---- fill B fragments once (validated) ----
    uint4* BF4 = (uint4*)(smw + OFF_BF);
    {
        const uint32_t* whi = (const uint32_t*)g_whi;
        const uint32_t* wlo = (const uint32_t*)g_wlo;
#pragma unroll 4
        for (int i = 0; i < 64; i++) {
            int idx = tid + i * 128;
            int l = idx & 31, wq = (idx >> 5) & 3, sp = (idx >> 7) & 1, kt = idx >> 8;
            const uint32_t* src = sp ? wlo : whi;
            int gid = l >> 2, tig = l & 3;
            int kw = kt * 8 + tig;
            uint4 v;
            {
                int nl = (2 * wq) * 8 + gid;
                int grow = (nl & 3) * Hdim + j0 + (nl >> 2);
                v.x = src[grow * 256 + kw];
                v.y = src[grow * 256 + kw + 4];
            }
            {
                int nl = (2 * wq + 1) * 8 + gid;
                int grow = (nl & 3) * Hdim + j0 + (nl >> 2);
                v.z = src[grow * 256 + kw];
                v.w = src[grow * 256 + kw + 4];
            }
            BF4[idx] = v;
        }
    }

    const int mrow = (lane & 7) + ((lane >> 3) & 1) * 8;
    const int halfk = (lane >> 4) & 1;
    const uint32_t a_woff = (uint32_t)(mrow * 260 + halfk * 4);
    const uint32_t ahi = smem_u32(smw) + (OFF_HHI + a_woff) * 4;
    const uint32_t alo = smem_u32(smw) + (OFF_HLO + a_woff) * 4;

    __nv_bfloat16* hs_hi = (__nv_bfloat16*)(smw + OFF_HSHI);
    __nv_bfloat16* hs_lo = (__nv_bfloat16*)(smw + OFF_HSLO);
    float*         hs_f  = (float*)(smw + OFF_HSF);

    const int q = lane & 3, r = lane >> 2;
    const int b_loc = r + ((q & 1) << 3);
    const int q2 = q >> 1;
    const int bglob = b0 + b_loc;

    float c0 = 0.f, c1 = 0.f;
    __syncthreads();   // BF4 ready

    // ---- hoist kt 0..15 B fragments into registers (loop-invariant) ----
    uint4 Brh[16], Brl[16];
#pragma unroll
    for (int kt = 0; kt < 16; kt++) {
        Brh[kt] = BF4[((kt * 2 + 0) * 4 + w) * 32 + lane];
        Brl[kt] = BF4[((kt * 2 + 1) * 4 + w) * 32 + lane];
    }

    for (int t = 0; t < Tlen; t++) {
        const int cur = t & 1, nxt = cur ^ 1;

        // ---- 1. prefetch this thread's 8 pre scalars (overlaps the spin) ----
        float pr[2][4];
#pragma unroll
        for (int n8 = 0; n8 < 2; n8++) {
            const float* p = g_pre + ((size_t)t * Bsz + bglob) * G4H + j0 + w * 4 + n8 * 2 + q2;
#pragma unroll
            for (int g = 0; g < 4; g++) pr[n8][g] = __ldg(p + g * Hdim);
        }

        // ---- 2. wait for h_t (single spinner per block) ----
        if (t > 0) {
            if (tid == 0) {
                unsigned tgt = (unsigned)t * GBLK;
                while (ld_acquire(cnt) < tgt) { }
            }
            __syncthreads();
        }

        const uint4* shi = (const uint4*)g_hh[cur] + b0 * 64;
        const uint4* slo = (const uint4*)g_hl[cur] + b0 * 64;

        // ---- 3a. stage K-half 0 (words q 0..31, both splits) ----
#pragma unroll
        for (int i = 0; i < 8; i++) {
            int idx = tid + i * 128;                 // 0..1023
            int sp = idx >> 9, rem = idx & 511;
            int row = rem >> 5, qq = rem & 31;
            const uint4* src = sp ? slo : shi;
            uint4 v = __ldcg(src + row * 64 + qq);
            *(uint4*)(smw + (sp ? OFF_HLO : OFF_HHI) + row * 260 + qq * 4) = v;
        }
        __syncthreads();

        // ---- 3b. issue K-half 1 LDGs into registers (completes under MMA) ----
        uint4 hbuf[8];
#pragma unroll
        for (int i = 0; i < 8; i++) {
            int idx = tid + i * 128;
            int sp = idx >> 9, rem = idx & 511;
            int row = rem >> 5, qq = 32 + (rem & 31);
            const uint4* src = sp ? slo : shi;
            hbuf[i] = __ldcg(src + row * 64 + qq);
        }

        // ---- 4a. MMA K-half 0 (kt 0..15) with register-resident B ----
        float d0[4] = {0.f, 0.f, 0.f, 0.f};
        float d1[4] = {0.f, 0.f, 0.f, 0.f};
#pragma unroll
        for (int kt = 0; kt < 16; kt++) {
            uint32_t ah[4], al[4];
            ldsm4(ah, ahi + kt * 32);
            ldsm4(al, alo + kt * 32);
            mma16816(d0, ah, Brh[kt].x, Brh[kt].y);
            mma16816(d0, ah, Brl[kt].x, Brl[kt].y);
            mma16816(d0, al, Brh[kt].x, Brh[kt].y);
            mma16816(d1, ah, Brh[kt].z, Brh[kt].w);
            mma16816(d1, ah, Brl[kt].z, Brl[kt].w);
            mma16816(d1, al, Brh[kt].z, Brh[kt].w);
        }

        // ---- 4b. commit K-half 1 to smem, sync, MMA (kt 16..31) from BF4 ----
#pragma unroll
        for (int i = 0; i < 8; i++) {
            int idx = tid + i * 128;
            int sp = idx >> 9, rem = idx & 511;
            int row = rem >> 5, qq = 32 + (rem & 31);
            *(uint4*)(smw + (sp ? OFF_HLO : OFF_HHI) + row * 260 + qq * 4) = hbuf[i];
        }
        __syncthreads();

#pragma unroll 8
        for (int kt = 16; kt < 32; kt++) {
            uint32_t ah[4], al[4];
            ldsm4(ah, ahi + kt * 32);
            ldsm4(al, alo + kt * 32);
            uint4 bh = BF4[((kt * 2 + 0) * 4 + w) * 32 + lane];
            uint4 bl = BF4[((kt * 2 + 1) * 4 + w) * 32 + lane];
            mma16816(d0, ah, bh.x, bh.y);
            mma16816(d0, ah, bl.x, bl.y);
            mma16816(d0, al, bh.x, bh.y);
            mma16816(d1, ah, bh.z, bh.w);
            mma16816(d1, ah, bl.z, bl.w);
            mma16816(d1, al, bh.z, bh.w);
        }

        // ---- 5. epilogue: compute cells, stage h/hi/lo into smem ----
#pragma unroll
        for (int n8 = 0; n8 < 2; n8++) {
            float* dd = n8 ? d1 : d0;
            float e0 = __shfl_xor_sync(0xffffffffu, dd[0], 1);
            float e1 = __shfl_xor_sync(0xffffffffu, dd[1], 1);
            float e2 = __shfl_xor_sync(0xffffffffu, dd[2], 1);
            float e3 = __shfl_xor_sync(0xffffffffu, dd[3], 1);
            float ai, af, ag, ao;
            if ((q & 1) == 0) { ai = dd[0]; af = dd[1]; ag = e0;    ao = e1;    }
            else              { ai = e2;    af = e3;    ag = dd[2]; ao = dd[3]; }
            ai += pr[n8][0]; af += pr[n8][1]; ag += pr[n8][2]; ao += pr[n8][3];

            float ig = fast_sigmoid(ai);
            float fg = fast_sigmoid(af);
            float gg = fast_tanh(ag);
            float og = fast_sigmoid(ao);
            float& c = n8 ? c1 : c0;
            c = fg * c + ig * gg;
            float h = og * fast_tanh(c);

            int ub = w * 4 + n8 * 2 + q2;                  // unit within block
            __nv_bfloat16 hhv = __float2bfloat16(h);
            hs_hi[b_loc * 16 + ub] = hhv;
            hs_lo[b_loc * 16 + ub] = __float2bfloat16(h - __bfloat162float(hhv));
            hs_f [b_loc * 16 + ub] = h;
            if (t == Tlen - 1) cn[(size_t)bglob * Hdim + j0 + ub] = c;
        }
        __syncthreads();   // hs_* ready

        // ---- 6. coalesced critical stores: h split (64 x uint4) ----
        if (tid < 64) {
            int row = (tid & 31) >> 1, qq = tid & 1;
            if (tid < 32) {
                uint4 v = ((const uint4*)hs_hi)[tid];
                *((uint4*)(g_hh[nxt] + (size_t)(b0 + row) * Hdim + j0) + qq) = v;
            } else {
                uint4 v = ((const uint4*)hs_lo)[tid - 32];
                *((uint4*)(g_hl[nxt] + (size_t)(b0 + row) * Hdim + j0) + qq) = v;
            }
        }
        __syncthreads();   // h-split stores performed block-wide

        // ---- 7. release (single arriver) ----
        if (t < Tlen - 1 && tid == 0) red_release_add(cnt);

        // ---- 8. off-critical-path coalesced out rows (+hn at the end) ----
        {
            int row = tid >> 3, k2 = tid & 7;
            float2 v = ((const float2*)hs_f)[tid];
            *(float2*)(out + (size_t)(b0 + row) * Tlen * Hdim + (size_t)t * Hdim
                       + j0 + k2 * 2) = v;
            if (t == Tlen - 1)
                *(float2*)(hn + (size_t)(b0 + row) * Hdim + j0 + k2 * 2) = v;
        }
    }
}

// ---------------- launch ----------------
extern "C" void kernel_launch(void* const* d_in, const int* in_sizes, int n_in,
                              void* d_out, int out_size) {
    const float* x    = (const float*)d_in[0];
    const float* w_ih = (const float*)d_in[1];
    const float* w_hh = (const float*)d_in[2];
    const float* b_ih = (const float*)d_in[3];
    const float* b_hh = (const float*)d_in[4];

    float* out = (float*)d_out;
    float* hn  = out + (size_t)Bsz * Tlen * Hdim;
    float* cn  = hn + (size_t)Bsz * Hdim;

    static const size_t GEMM_SMEM = 4 * TILE_W * sizeof(uint32_t);
    static const size_t SCAN_SMEM = SCAN_WORDS * sizeof(uint32_t);   // 166400 B
    cudaFuncSetAttribute(gemm_pre, cudaFuncAttributeMaxDynamicSharedMemorySize,
                         (int)GEMM_SMEM);
    cudaFuncSetAttribute(lstm_scan, cudaFuncAttributeMaxDynamicSharedMemorySize,
                         (int)SCAN_SMEM);

    // capture model: ncu -s 5 -c 1 lands on user-launch index 3 -> lstm_scan
    prep_kernel<<<(Bsz * Tlen * Idim) / 256, 256>>>(x, w_ih, w_hh);
    gemm_pre<<<dim3(G4H / 128, (Bsz * Tlen) / 128), 256, GEMM_SMEM>>>(b_ih, b_hh);
    probe_a<<<1, 32>>>();
    lstm_scan<<<NBLK, 128, SCAN_SMEM>>>(out, hn, cn);
}